// round 3
// baseline (speedup 1.0000x reference)
#include <cuda_runtime.h>
#include <cuda_fp16.h>
#include <cstdint>

// Problem dims (fixed by reference setup_inputs)
#define CDIM 32
#define NDIM 32
#define RDIM 256
#define LDIM 256
#define DDIM 512

// fp16 scratch copies of inputs + precomputed contract row norms
__device__ __half g_con_h[CDIM * RDIM * DDIM];   // 8 MB
__device__ __half g_law_h[NDIM * LDIM * DDIM];   // 8 MB
__device__ float  g_w1[CDIM * RDIM];

// ---------------- smem layout (bytes) ----------------
#define PSTR      264                     // P row stride in halves (256 + 8 pad)
#define P_BYTES   (LDIM * PSTR * 2)       // 135168
#define ST1       72                      // staging row stride in halves (64 + 8 pad)
#define LAW1_OFF  (P_BYTES)                       // 2 x 64*72*2   = 18432
#define CON1_OFF  (LAW1_OFF + 2 * 64 * ST1 * 2)   // 2 x 256*72*2  = 73728
#define LAW2_OFF  (P_BYTES)                       // phase-2 reuse of staging area
#define CON2_OFF  (P_BYTES + 256 * ST1 * 2)
#define W12_OFF   (CON1_OFF + 2 * 256 * ST1 * 2)  // 227328
#define W2_OFF    (W12_OFF + 256 * 4)
#define RED_OFF   (W2_OFF + 256 * 4)
#define SMEM_TOTAL (RED_OFF + 32 * 4)             // 229504 <= 232448 (227KB)

#define LEAKY 0.1f
#define SMOOTH 4.0f
#define LLSE 6.0f
#define SCALE_INV_SQRTD 0.04419417382415922f   // 1/sqrt(512)

// ---------------- PTX helpers ----------------
__device__ __forceinline__ uint32_t s2u(const void* p) {
    return (uint32_t)__cvta_generic_to_shared(p);
}
__device__ __forceinline__ void cp16(uint32_t dst, const void* src) {
    asm volatile("cp.async.cg.shared.global [%0], [%1], 16;\n" :: "r"(dst), "l"(src));
}
__device__ __forceinline__ void cp_commit() {
    asm volatile("cp.async.commit_group;\n");
}
__device__ __forceinline__ void ldsm_x4(uint32_t& r0, uint32_t& r1, uint32_t& r2, uint32_t& r3, uint32_t a) {
    asm volatile("ldmatrix.sync.aligned.m8n8.x4.shared.b16 {%0,%1,%2,%3}, [%4];\n"
                 : "=r"(r0), "=r"(r1), "=r"(r2), "=r"(r3) : "r"(a));
}
__device__ __forceinline__ void ldsm_x4t(uint32_t& r0, uint32_t& r1, uint32_t& r2, uint32_t& r3, uint32_t a) {
    asm volatile("ldmatrix.sync.aligned.m8n8.x4.trans.shared.b16 {%0,%1,%2,%3}, [%4];\n"
                 : "=r"(r0), "=r"(r1), "=r"(r2), "=r"(r3) : "r"(a));
}
__device__ __forceinline__ void mma16816(float* c,
                                         uint32_t a0, uint32_t a1, uint32_t a2, uint32_t a3,
                                         uint32_t b0, uint32_t b1) {
    asm volatile("mma.sync.aligned.m16n8k16.row.col.f32.f16.f16.f32 "
                 "{%0,%1,%2,%3}, {%4,%5,%6,%7}, {%8,%9}, {%0,%1,%2,%3};\n"
                 : "+f"(c[0]), "+f"(c[1]), "+f"(c[2]), "+f"(c[3])
                 : "r"(a0), "r"(a1), "r"(a2), "r"(a3), "r"(b0), "r"(b1));
}

// ---------------- pre-pass kernels ----------------
// One block per (c,r) row: fp32 -> fp16 convert + row norm.
__global__ void ctl_prep_con(const float* __restrict__ con) {
    int row = blockIdx.x;           // 0..8191
    int t = threadIdx.x;            // 128
    const float4* src = reinterpret_cast<const float4*>(con + (size_t)row * DDIM);
    float4 v = src[t];
    __half2* dst = reinterpret_cast<__half2*>(g_con_h + (size_t)row * DDIM);
    dst[2 * t + 0] = __floats2half2_rn(v.x, v.y);
    dst[2 * t + 1] = __floats2half2_rn(v.z, v.w);
    float ss = v.x * v.x + v.y * v.y + v.z * v.z + v.w * v.w;
    #pragma unroll
    for (int o = 16; o; o >>= 1) ss += __shfl_xor_sync(0xffffffffu, ss, o);
    __shared__ float red[4];
    if ((t & 31) == 0) red[t >> 5] = ss;
    __syncthreads();
    if (t == 0) g_w1[row] = sqrtf(red[0] + red[1] + red[2] + red[3]);
}

__global__ void ctl_prep_law(const float* __restrict__ law) {
    int row = blockIdx.x;
    int t = threadIdx.x;
    const float4* src = reinterpret_cast<const float4*>(law + (size_t)row * DDIM);
    float4 v = src[t];
    __half2* dst = reinterpret_cast<__half2*>(g_law_h + (size_t)row * DDIM);
    dst[2 * t + 0] = __floats2half2_rn(v.x, v.y);
    dst[2 * t + 1] = __floats2half2_rn(v.z, v.w);
}

// ---------------- main fused kernel: one CTA per (n, c) ----------------
__global__ __launch_bounds__(256, 1)
void ctl_main(const int* __restrict__ lens, float* __restrict__ out) {
    extern __shared__ char smem[];
    const int c = blockIdx.x;
    const int n = blockIdx.y;
    const int tid = threadIdx.x;
    const int wid = tid >> 5;
    const int lane = tid & 31;
    const int g = lane >> 2;      // groupID (row within 8)
    const int t4 = lane & 3;

    __half* P = (__half*)smem;                                 // [256][264] fp16 attn
    __half* law1 = (__half*)(smem + LAW1_OFF);                 // [2][64][72]
    __half* con1 = (__half*)(smem + CON1_OFF);                 // [2][256][72]
    const __half* lawg = g_law_h + (size_t)n * LDIM * DDIM;
    const __half* cong = g_con_h + (size_t)c * RDIM * DDIM;
    const int len = lens[n];

    // ================= Phase 1: attn = softmax-ops(laws @ con^T) into P =================
    const int wl = wid >> 1;      // 0..3 -> 16 l-rows each
    const int wr = wid & 1;       // 0..1 -> 128 r-cols each

    for (int lc = 0; lc < 4; lc++) {
        const int l0 = lc * 64;

        auto issue = [&](int kt) {
            int buf = kt & 1;
            __half* lb = law1 + buf * (64 * ST1);
            __half* cb = con1 + buf * (256 * ST1);
            #pragma unroll
            for (int i = 0; i < 2; i++) {          // laws: 64 rows x 8 chunks
                int id = tid + 256 * i;
                int row = id >> 3, ch = id & 7;
                cp16(s2u(lb + row * ST1 + ch * 8),
                     lawg + (size_t)(l0 + row) * DDIM + kt * 64 + ch * 8);
            }
            #pragma unroll
            for (int i = 0; i < 8; i++) {          // contracts: 256 rows x 8 chunks
                int id = tid + 256 * i;
                int row = id >> 3, ch = id & 7;
                cp16(s2u(cb + row * ST1 + ch * 8),
                     cong + (size_t)row * DDIM + kt * 64 + ch * 8);
            }
            cp_commit();
        };

        float acc[64];
        #pragma unroll
        for (int i = 0; i < 64; i++) acc[i] = 0.f;

        issue(0);
        for (int kt = 0; kt < 8; kt++) {
            if (kt < 7) {
                issue(kt + 1);
                asm volatile("cp.async.wait_group 1;\n");
            } else {
                asm volatile("cp.async.wait_group 0;\n");
            }
            __syncthreads();
            int buf = kt & 1;
            const __half* lb = law1 + buf * (64 * ST1);
            const __half* cb = con1 + buf * (256 * ST1);
            #pragma unroll
            for (int ks = 0; ks < 4; ks++) {
                uint32_t a0, a1, a2, a3;
                {
                    int row = wl * 16 + (lane & 15);
                    int col = ks * 16 + (lane >> 4) * 8;
                    ldsm_x4(a0, a1, a2, a3, s2u(lb + row * ST1 + col));
                }
                #pragma unroll
                for (int np = 0; np < 8; np++) {
                    uint32_t b0, b1, b2, b3;
                    int n0 = wr * 128 + np * 16;
                    int row = n0 + (lane & 7) + ((lane >> 4) << 3);
                    int col = ks * 16 + ((lane >> 3) & 1) * 8;
                    ldsm_x4(b0, b1, b2, b3, s2u(cb + row * ST1 + col));
                    mma16816(acc + (np * 2 + 0) * 4, a0, a1, a2, a3, b0, b1);
                    mma16816(acc + (np * 2 + 1) * 4, a0, a1, a2, a3, b2, b3);
                }
            }
            __syncthreads();
        }

        // scale + leaky-relu, store S chunk into P (fp16)
        {
            int lrow0 = l0 + wl * 16 + g;
            #pragma unroll
            for (int nt = 0; nt < 16; nt++) {
                int rb = wr * 128 + nt * 8 + 2 * t4;
                float v0 = acc[nt * 4 + 0] * SCALE_INV_SQRTD;
                float v1 = acc[nt * 4 + 1] * SCALE_INV_SQRTD;
                float v2 = acc[nt * 4 + 2] * SCALE_INV_SQRTD;
                float v3 = acc[nt * 4 + 3] * SCALE_INV_SQRTD;
                v0 = (v0 >= 0.f) ? v0 : LEAKY * v0;
                v1 = (v1 >= 0.f) ? v1 : LEAKY * v1;
                v2 = (v2 >= 0.f) ? v2 : LEAKY * v2;
                v3 = (v3 >= 0.f) ? v3 : LEAKY * v3;
                *(__half2*)&P[(size_t)lrow0 * PSTR + rb]       = __floats2half2_rn(v0, v1);
                *(__half2*)&P[(size_t)(lrow0 + 8) * PSTR + rb] = __floats2half2_rn(v2, v3);
            }
        }
        __syncthreads();

        // row ops (per l-row over full R): l2norm -> softmax -> *SMOOTH -> mask
        for (int rr = 0; rr < 8; rr++) {
            int l = l0 + wid * 8 + rr;
            __half2* prow = (__half2*)&P[(size_t)l * PSTR];
            float v[8];
            float ss = 0.f;
            #pragma unroll
            for (int j = 0; j < 4; j++) {
                __half2 h = prow[lane + 32 * j];
                float x = __low2float(h), y = __high2float(h);
                v[2 * j] = x; v[2 * j + 1] = y;
                ss += x * x + y * y;
            }
            #pragma unroll
            for (int o = 16; o; o >>= 1) ss += __shfl_xor_sync(0xffffffffu, ss, o);
            float inv = 1.f / (sqrtf(ss) + 1e-8f);
            float es = 0.f;
            #pragma unroll
            for (int j = 0; j < 8; j++) {
                v[j] = __expf(v[j] * inv);
                es += v[j];
            }
            #pragma unroll
            for (int o = 16; o; o >>= 1) es += __shfl_xor_sync(0xffffffffu, es, o);
            float zf = (l < len) ? (SMOOTH / es) : 0.f;
            #pragma unroll
            for (int j = 0; j < 4; j++)
                prow[lane + 32 * j] = __floats2half2_rn(v[2 * j] * zf, v[2 * j + 1] * zf);
        }
        __syncthreads();
    }

    // ================= Phase 2: wlaw = P^T @ laws, fused cosine partials =================
    __half* law2 = (__half*)(smem + LAW2_OFF);   // [256][72]
    __half* con2 = (__half*)(smem + CON2_OFF);   // [256][72]
    float* w12s = (float*)(smem + W12_OFF);
    float* w2s  = (float*)(smem + W2_OFF);

    float w12a[4] = {0.f, 0.f, 0.f, 0.f};
    float w2a[4]  = {0.f, 0.f, 0.f, 0.f};
    const int rbase = wid * 32;

    for (int dt = 0; dt < 8; dt++) {
        #pragma unroll
        for (int i = 0; i < 8; i++) {
            int id = tid + 256 * i;
            int row = id >> 3, ch = id & 7;
            cp16(s2u(law2 + row * ST1 + ch * 8),
                 lawg + (size_t)row * DDIM + dt * 64 + ch * 8);
        }
        #pragma unroll
        for (int i = 0; i < 8; i++) {
            int id = tid + 256 * i;
            int row = id >> 3, ch = id & 7;
            cp16(s2u(con2 + row * ST1 + ch * 8),
                 cong + (size_t)row * DDIM + dt * 64 + ch * 8);
        }
        cp_commit();
        asm volatile("cp.async.wait_group 0;\n");
        __syncthreads();

        float acc[64];
        #pragma unroll
        for (int i = 0; i < 64; i++) acc[i] = 0.f;

        #pragma unroll 4
        for (int ks = 0; ks < 16; ks++) {
            int l0k = ks * 16;
            uint32_t a[2][4];
            #pragma unroll
            for (int mt = 0; mt < 2; mt++) {
                int r0 = rbase + mt * 16;
                int row = l0k + (lane & 7) + ((lane & 16) >> 1);
                int col = r0 + (lane & 8);
                ldsm_x4t(a[mt][0], a[mt][1], a[mt][2], a[mt][3],
                         s2u(&P[(size_t)row * PSTR + col]));
            }
            #pragma unroll
            for (int np = 0; np < 4; np++) {
                uint32_t b0, b1, b2, b3;
                int d0 = np * 16;
                int row = l0k + (lane & 7) + (lane & 8);
                int col = d0 + ((lane & 16) >> 1);
                ldsm_x4t(b0, b1, b2, b3, s2u(&law2[row * ST1 + col]));
                mma16816(acc + (0 * 8 + np * 2 + 0) * 4, a[0][0], a[0][1], a[0][2], a[0][3], b0, b1);
                mma16816(acc + (0 * 8 + np * 2 + 1) * 4, a[0][0], a[0][1], a[0][2], a[0][3], b2, b3);
                mma16816(acc + (1 * 8 + np * 2 + 0) * 4, a[1][0], a[1][1], a[1][2], a[1][3], b0, b1);
                mma16816(acc + (1 * 8 + np * 2 + 1) * 4, a[1][0], a[1][1], a[1][2], a[1][3], b2, b3);
            }
        }

        // cosine partials for this d-tile
        #pragma unroll
        for (int mt = 0; mt < 2; mt++) {
            #pragma unroll
            for (int s = 0; s < 2; s++) {
                int r = rbase + mt * 16 + g + 8 * s;
                float pw12 = 0.f, pw2 = 0.f;
                #pragma unroll
                for (int nt = 0; nt < 8; nt++) {
                    float o0 = acc[(mt * 8 + nt) * 4 + 2 * s + 0];
                    float o1 = acc[(mt * 8 + nt) * 4 + 2 * s + 1];
                    __half2 chh = *(const __half2*)&con2[r * ST1 + nt * 8 + 2 * t4];
                    pw12 += o0 * __low2float(chh) + o1 * __high2float(chh);
                    pw2  += o0 * o0 + o1 * o1;
                }
                pw12 += __shfl_xor_sync(0xffffffffu, pw12, 1);
                pw12 += __shfl_xor_sync(0xffffffffu, pw12, 2);
                pw2  += __shfl_xor_sync(0xffffffffu, pw2, 1);
                pw2  += __shfl_xor_sync(0xffffffffu, pw2, 2);
                w12a[mt * 2 + s] += pw12;
                w2a[mt * 2 + s]  += pw2;
            }
        }
        __syncthreads();   // before next tile overwrites law2/con2
    }

    if (t4 == 0) {
        #pragma unroll
        for (int mt = 0; mt < 2; mt++)
            #pragma unroll
            for (int s = 0; s < 2; s++) {
                int r = rbase + mt * 16 + g + 8 * s;
                w12s[r] = w12a[mt * 2 + s];
                w2s[r]  = w2a[mt * 2 + s];
            }
    }
    __syncthreads();

    // ================= sim + LogSumExp over regions =================
    {
        int r = tid;
        float w2 = sqrtf(w2s[r]);
        float denom = fmaxf(g_w1[c * RDIM + r] * w2, 1e-8f);
        float sim = w12s[r] / denom;
        float e = __expf(LLSE * sim);
        #pragma unroll
        for (int o = 16; o; o >>= 1) e += __shfl_xor_sync(0xffffffffu, e, o);
        float* red = (float*)(smem + RED_OFF);
        if (lane == 0) red[wid] = e;
        __syncthreads();
        if (tid == 0) {
            float s = 0.f;
            #pragma unroll
            for (int i = 0; i < 8; i++) s += red[i];
            out[c * NDIM + n] = logf(s) * (1.0f / LLSE);
        }
    }
}

// ---------------- launch ----------------
extern "C" void kernel_launch(void* const* d_in, const int* in_sizes, int n_in,
                              void* d_out, int out_size) {
    const float* contracts = (const float*)d_in[0];   // [32,256,512] fp32
    const float* laws      = (const float*)d_in[1];   // [32,256,512] fp32
    const int*   law_lens  = (const int*)d_in[2];     // [32] int32
    float* out = (float*)d_out;                        // [32,32] fp32

    cudaFuncSetAttribute(ctl_main, cudaFuncAttributeMaxDynamicSharedMemorySize, SMEM_TOTAL);

    ctl_prep_con<<<CDIM * RDIM, 128>>>(contracts);
    ctl_prep_law<<<NDIM * LDIM, 128>>>(laws);
    ctl_main<<<dim3(CDIM, NDIM), 256, SMEM_TOTAL>>>(law_lens, out);
}